// round 3
// baseline (speedup 1.0000x reference)
#include <cuda_runtime.h>

// StrictOrthogonal via CholeskyQR2, single persistent kernel.
// 128 CTAs (all co-resident: grid <= 148 SMs, wave-1 placement) x 256 threads.
// Per-CTA 128x32 complex chunk lives in SMEM for the whole kernel:
//   A read once, A1 never hits global, Out written once.
// Grid barriers: red-add arrive + nanosleep-backoff spin (4 total).

#define M_ROWS 16384
#define R_COLS 32
#define CHUNK  128
#define NCTA   128
#define TPB    256

__device__ float    g_part[NCTA * 2048];   // per-CTA Gram partials (1 MB)
__device__ float2   g_S[R_COLS * R_COLS];  // reduced Gram
__device__ unsigned g_bar[4];              // barrier counters (memset each launch)

// ---------------------------------------------------------------------------
__device__ __forceinline__ void grid_barrier(int id) {
    __syncthreads();                       // all CTA threads done with prior phase
    if (threadIdx.x == 0) {
        __threadfence();                   // make this CTA's global writes visible
        atomicAdd(&g_bar[id], 1u);         // return unused -> REDG (no-return)
        volatile unsigned* p = &g_bar[id];
        while (*p < NCTA) __nanosleep(32);
        __threadfence();                   // order spin-read before subsequent reads
    }
    __syncthreads();
}

// ---------------------------------------------------------------------------
// Gram partial over the CTA's SMEM chunk. 4 groups of 64 threads, each group
// covers 32 rows with an 8x8 grid of 4x4 complex tiles. Partials combined
// in-SMEM (fixed order) into g_part[blk].
// ---------------------------------------------------------------------------
__device__ __forceinline__ void gram_phase(const float2* __restrict__ chunk,
                                           float* __restrict__ buf, int blk) {
    const int tid = threadIdx.x;
    const int g  = tid >> 6;
    const int t  = tid & 63;
    const int ti = t & 7;
    const int tj = t >> 3;
    const int i0 = ti * 4;
    const int j0 = tj * 4;
    const int r0 = g * 32;

    float2 acc[4][4];
#pragma unroll
    for (int p = 0; p < 4; ++p)
#pragma unroll
        for (int q = 0; q < 4; ++q) acc[p][q] = make_float2(0.f, 0.f);

#pragma unroll 4
    for (int r = 0; r < 32; ++r) {
        const float4* rowp = reinterpret_cast<const float4*>(&chunk[(r0 + r) * R_COLS]);
        float4 av0 = rowp[ti * 2], av1 = rowp[ti * 2 + 1];
        float4 bv0 = rowp[tj * 2], bv1 = rowp[tj * 2 + 1];
        float2 a[4] = { {av0.x, av0.y}, {av0.z, av0.w}, {av1.x, av1.y}, {av1.z, av1.w} };
        float2 b[4] = { {bv0.x, bv0.y}, {bv0.z, bv0.w}, {bv1.x, bv1.y}, {bv1.z, bv1.w} };
#pragma unroll
        for (int p = 0; p < 4; ++p)
#pragma unroll
            for (int q = 0; q < 4; ++q) {
                acc[p][q].x = fmaf(a[p].x, b[q].x, acc[p][q].x);
                acc[p][q].x = fmaf(a[p].y, b[q].y, acc[p][q].x);
                acc[p][q].y = fmaf(a[p].x, b[q].y, acc[p][q].y);
                acc[p][q].y = fmaf(-a[p].y, b[q].x, acc[p][q].y);
            }
    }
    __syncthreads();

    // Combine groups: sum = (g0+g1) + (g2+g3), via one 8KB buffer, fixed order.
#define ST_ACC() \
    { _Pragma("unroll") for (int p = 0; p < 4; ++p) _Pragma("unroll") \
      for (int q = 0; q < 4; ++q) { \
          int e = ((i0 + p) * R_COLS + (j0 + q)) * 2; \
          buf[e] = acc[p][q].x; buf[e + 1] = acc[p][q].y; } }
#define ADD_ACC() \
    { _Pragma("unroll") for (int p = 0; p < 4; ++p) _Pragma("unroll") \
      for (int q = 0; q < 4; ++q) { \
          int e = ((i0 + p) * R_COLS + (j0 + q)) * 2; \
          acc[p][q].x += buf[e]; acc[p][q].y += buf[e + 1]; } }

    if (g == 1) ST_ACC();
    __syncthreads();
    if (g == 0) ADD_ACC();
    __syncthreads();
    if (g == 3) ST_ACC();
    __syncthreads();
    if (g == 2) ADD_ACC();
    __syncthreads();
    if (g == 2) ST_ACC();
    __syncthreads();
    if (g == 0) {
        ADD_ACC();
#pragma unroll
        for (int p = 0; p < 4; ++p)
#pragma unroll
            for (int q = 0; q < 4; ++q) {
                int e = ((i0 + p) * R_COLS + (j0 + q)) * 2;
                g_part[blk * 2048 + e]     = acc[p][q].x;
                g_part[blk * 2048 + e + 1] = acc[p][q].y;
            }
    }
#undef ST_ACC
#undef ADD_ACC
}

// ---------------------------------------------------------------------------
// Reduce: 2048 elements, 128 partials each. CTA b owns 16 elements; each
// element reduced by 16 lanes (8 strided loads + fixed shuffle tree).
// ---------------------------------------------------------------------------
__device__ __forceinline__ void reduce_phase(int blk) {
    const int tid = threadIdx.x;
    const int e = blk * 16 + (tid >> 4);
    const int l = tid & 15;
    float s = 0.f;
#pragma unroll
    for (int k = 0; k < 8; ++k)
        s += __ldcg(&g_part[(l + 16 * k) * 2048 + e]);
    s += __shfl_down_sync(0xffffffffu, s, 8);
    s += __shfl_down_sync(0xffffffffu, s, 4);
    s += __shfl_down_sync(0xffffffffu, s, 2);
    s += __shfl_down_sync(0xffffffffu, s, 1);
    if (l == 0) reinterpret_cast<float*>(g_S)[e] = s;
}

// ---------------------------------------------------------------------------
// Per-CTA (redundant) Cholesky of g_S + trisolve; W = R^{-1} -> smem wbuf.
// Warp 0 only. wbuf aliases the gram combine buffer (8 KB).
// ---------------------------------------------------------------------------
__device__ __forceinline__ void cholinv_phase(float2* __restrict__ wbuf) {
    if (threadIdx.x >= 32) return;
    const unsigned FULL = 0xffffffffu;
    const int r = threadIdx.x;

    float2 row[R_COLS];
#pragma unroll
    for (int c = 0; c < R_COLS; ++c) row[c] = __ldcg(&g_S[r * R_COLS + c]);

#pragma unroll
    for (int k = 0; k < R_COLS; ++k) {
        float dkk  = __shfl_sync(FULL, row[k].x, k);
        float invs = rsqrtf(dkk);
        float2 l;
        l.x = row[k].x * invs;
        l.y = row[k].y * invs;
        row[k] = l;
#pragma unroll
        for (int j = k + 1; j < R_COLS; ++j) {
            float lx = __shfl_sync(FULL, l.x, j);
            float ly = __shfl_sync(FULL, l.y, j);
            row[j].x -= l.x * lx + l.y * ly;
            row[j].y -= l.y * lx - l.x * ly;
        }
    }

    float2 (*L)[R_COLS] = reinterpret_cast<float2(*)[R_COLS]>(wbuf);
#pragma unroll
    for (int k = 0; k < R_COLS; ++k) L[r][k] = row[k];
    __syncwarp();

    const int c = r;
    float2 x[R_COLS];
#pragma unroll
    for (int rr = 0; rr < R_COLS; ++rr) {
        float2 s = (rr == c) ? make_float2(1.f, 0.f) : make_float2(0.f, 0.f);
#pragma unroll
        for (int k = 0; k < rr; ++k) {
            float2 lv = L[rr][k];
            s.x -= lv.x * x[k].x - lv.y * x[k].y;
            s.y -= lv.x * x[k].y + lv.y * x[k].x;
        }
        float invd = 1.0f / L[rr][rr].x;
        x[rr] = make_float2(s.x * invd, s.y * invd);
    }
    __syncwarp();   // all lanes done reading L before overwriting with W

    // W[c][j] = conj(x[j]); x[j]=0 for j<c -> W exactly upper triangular.
#pragma unroll
    for (int j = 0; j < R_COLS; ++j)
        wbuf[c * R_COLS + j] = make_float2(x[j].x, -x[j].y);
}

// ---------------------------------------------------------------------------
// Apply: row' = row * W (W upper tri, in smem). 2 threads per row:
// half 0 -> cols 0..15, half 1 -> cols 16..31. dst may be the chunk itself.
// ---------------------------------------------------------------------------
__device__ __forceinline__ void apply_phase(float2* __restrict__ chunk,
                                            const float2* __restrict__ W,
                                            float2* __restrict__ dst, int dstride) {
    const int tid  = threadIdx.x;
    const int row  = tid >> 1;
    const int half = tid & 1;

    float2 a[R_COLS];
    const float4* rp = reinterpret_cast<const float4*>(&chunk[row * R_COLS]);
#pragma unroll
    for (int i = 0; i < 16; ++i) {
        float4 v = rp[i];
        a[2 * i]     = make_float2(v.x, v.y);
        a[2 * i + 1] = make_float2(v.z, v.w);
    }
    __syncthreads();   // all reads of chunk done before any in-place writes

    float2* out = dst + row * dstride;
    if (half == 0) {
#pragma unroll
        for (int j = 0; j < 16; ++j) {
            float2 s = make_float2(0.f, 0.f);
#pragma unroll
            for (int i = 0; i <= j; ++i) {
                float2 w = W[i * R_COLS + j];
                s.x = fmaf(a[i].x, w.x, s.x);
                s.x = fmaf(-a[i].y, w.y, s.x);
                s.y = fmaf(a[i].x, w.y, s.y);
                s.y = fmaf(a[i].y, w.x, s.y);
            }
            out[j] = s;
        }
    } else {
#pragma unroll
        for (int j = 16; j < 32; ++j) {
            float2 s = make_float2(0.f, 0.f);
#pragma unroll
            for (int i = 0; i <= j; ++i) {
                float2 w = W[i * R_COLS + j];
                s.x = fmaf(a[i].x, w.x, s.x);
                s.x = fmaf(-a[i].y, w.y, s.x);
                s.y = fmaf(a[i].x, w.y, s.y);
                s.y = fmaf(a[i].y, w.x, s.y);
            }
            out[j] = s;
        }
    }
    __syncthreads();
}

// ---------------------------------------------------------------------------
__global__ __launch_bounds__(TPB, 1) void fused_cholqr2(const float2* __restrict__ A,
                                                        float2* __restrict__ Out) {
    __shared__ float2 chunk[CHUNK * R_COLS];   // 32 KB — CTA's rows, resident
    __shared__ float  scratch[2048];           // 8 KB — gram buf / L / W

    const int tid = threadIdx.x;
    const int blk = blockIdx.x;

    // Stage chunk from global (only read of A).
    {
        const float4* src = reinterpret_cast<const float4*>(A + (size_t)blk * CHUNK * R_COLS);
        float4* dst = reinterpret_cast<float4*>(chunk);
#pragma unroll
        for (int i = 0; i < 8; ++i) dst[tid + TPB * i] = src[tid + TPB * i];
    }
    __syncthreads();

    float2* W = reinterpret_cast<float2*>(scratch);

    // ---- pass 1 ----
    gram_phase(chunk, scratch, blk);
    grid_barrier(0);
    reduce_phase(blk);
    grid_barrier(1);
    cholinv_phase(W);
    __syncthreads();
    apply_phase(chunk, W, chunk, R_COLS);      // A1 in place, stays in SMEM

    // ---- pass 2 ----
    gram_phase(chunk, scratch, blk);
    grid_barrier(2);
    reduce_phase(blk);
    grid_barrier(3);
    cholinv_phase(W);
    __syncthreads();
    apply_phase(chunk, W, Out + (size_t)blk * CHUNK * R_COLS, R_COLS);
}

// ---------------------------------------------------------------------------
extern "C" void kernel_launch(void* const* d_in, const int* in_sizes, int n_in,
                              void* d_out, int out_size) {
    (void)in_sizes; (void)n_in; (void)out_size;
    const float2* A = reinterpret_cast<const float2*>(d_in[0]);
    float2* Out = reinterpret_cast<float2*>(d_out);

    void* barp = nullptr;
    cudaGetSymbolAddress(&barp, g_bar);
    cudaMemsetAsync(barp, 0, sizeof(unsigned) * 4);

    fused_cholqr2<<<NCTA, TPB>>>(A, Out);
}

// round 4
// speedup vs baseline: 2.0796x; 2.0796x over previous
#include <cuda_runtime.h>

// StrictOrthogonal via CholeskyQR1 (single pass), persistent kernel.
// Input is Gaussian (kappa ~= 1.09): one fp32 Cholesky-QR pass has
// orthogonality defect ~1e-5, threshold is 1e-3. 128 CTAs x 256 threads,
// all co-resident (grid <= 148 SMs) -> software grid barrier is safe.
// Per-CTA 128x32 complex chunk resident in SMEM: A read once, Out written
// once (coalesced float4). Two grid barriers total.

#define M_ROWS 16384
#define R_COLS 32
#define CHUNK  128
#define NCTA   128
#define TPB    256

__device__ float    g_part[NCTA * 2048];   // per-CTA Gram partials (1 MB)
__device__ float2   g_S[R_COLS * R_COLS];  // reduced Gram
__device__ unsigned g_bar[2];              // barrier counters (memset per launch)

// ---------------------------------------------------------------------------
__device__ __forceinline__ void grid_barrier(int id) {
    __syncthreads();                       // CTA done with prior phase
    if (threadIdx.x == 0) {
        __threadfence();                   // publish this CTA's global writes
        atomicAdd(&g_bar[id], 1u);         // return unused -> no-return reduce
        volatile unsigned* p = &g_bar[id];
        while (*p < NCTA) __nanosleep(32);
        __threadfence();
    }
    __syncthreads();
}

// ---------------------------------------------------------------------------
// Gram partial over the CTA's SMEM chunk. 4 groups of 64 threads; each group
// covers 32 rows with an 8x8 grid of 4x4 complex tiles. Group partials
// combined in-SMEM (fixed order) -> g_part[blk].
// ---------------------------------------------------------------------------
__device__ __forceinline__ void gram_phase(const float2* __restrict__ chunk,
                                           float* __restrict__ buf, int blk) {
    const int tid = threadIdx.x;
    const int g  = tid >> 6;
    const int t  = tid & 63;
    const int ti = t & 7;
    const int tj = t >> 3;
    const int i0 = ti * 4;
    const int j0 = tj * 4;
    const int r0 = g * 32;

    float2 acc[4][4];
#pragma unroll
    for (int p = 0; p < 4; ++p)
#pragma unroll
        for (int q = 0; q < 4; ++q) acc[p][q] = make_float2(0.f, 0.f);

#pragma unroll 4
    for (int r = 0; r < 32; ++r) {
        const float4* rowp = reinterpret_cast<const float4*>(&chunk[(r0 + r) * R_COLS]);
        float4 av0 = rowp[ti * 2], av1 = rowp[ti * 2 + 1];
        float4 bv0 = rowp[tj * 2], bv1 = rowp[tj * 2 + 1];
        float2 a[4] = { {av0.x, av0.y}, {av0.z, av0.w}, {av1.x, av1.y}, {av1.z, av1.w} };
        float2 b[4] = { {bv0.x, bv0.y}, {bv0.z, bv0.w}, {bv1.x, bv1.y}, {bv1.z, bv1.w} };
#pragma unroll
        for (int p = 0; p < 4; ++p)
#pragma unroll
            for (int q = 0; q < 4; ++q) {
                acc[p][q].x = fmaf(a[p].x, b[q].x, acc[p][q].x);
                acc[p][q].x = fmaf(a[p].y, b[q].y, acc[p][q].x);
                acc[p][q].y = fmaf(a[p].x, b[q].y, acc[p][q].y);
                acc[p][q].y = fmaf(-a[p].y, b[q].x, acc[p][q].y);
            }
    }
    __syncthreads();

#define ST_ACC() \
    { _Pragma("unroll") for (int p = 0; p < 4; ++p) _Pragma("unroll") \
      for (int q = 0; q < 4; ++q) { \
          int e = ((i0 + p) * R_COLS + (j0 + q)) * 2; \
          buf[e] = acc[p][q].x; buf[e + 1] = acc[p][q].y; } }
#define ADD_ACC() \
    { _Pragma("unroll") for (int p = 0; p < 4; ++p) _Pragma("unroll") \
      for (int q = 0; q < 4; ++q) { \
          int e = ((i0 + p) * R_COLS + (j0 + q)) * 2; \
          acc[p][q].x += buf[e]; acc[p][q].y += buf[e + 1]; } }

    if (g == 1) ST_ACC();
    __syncthreads();
    if (g == 0) ADD_ACC();
    __syncthreads();
    if (g == 3) ST_ACC();
    __syncthreads();
    if (g == 2) ADD_ACC();
    __syncthreads();
    if (g == 2) ST_ACC();
    __syncthreads();
    if (g == 0) {
        ADD_ACC();
#pragma unroll
        for (int p = 0; p < 4; ++p)
#pragma unroll
            for (int q = 0; q < 4; ++q) {
                int e = ((i0 + p) * R_COLS + (j0 + q)) * 2;
                g_part[blk * 2048 + e]     = acc[p][q].x;
                g_part[blk * 2048 + e + 1] = acc[p][q].y;
            }
    }
#undef ST_ACC
#undef ADD_ACC
}

// ---------------------------------------------------------------------------
// Reduce: 2048 elements x 128 partials. CTA b owns 16 elements; each element
// reduced by 16 lanes (8 strided __ldcg loads + fixed shuffle tree).
// ---------------------------------------------------------------------------
__device__ __forceinline__ void reduce_phase(int blk) {
    const int tid = threadIdx.x;
    const int e = blk * 16 + (tid >> 4);
    const int l = tid & 15;
    float s = 0.f;
#pragma unroll
    for (int k = 0; k < 8; ++k)
        s += __ldcg(&g_part[(l + 16 * k) * 2048 + e]);
    s += __shfl_down_sync(0xffffffffu, s, 8);
    s += __shfl_down_sync(0xffffffffu, s, 4);
    s += __shfl_down_sync(0xffffffffu, s, 2);
    s += __shfl_down_sync(0xffffffffu, s, 1);
    if (l == 0) reinterpret_cast<float*>(g_S)[e] = s;
}

// ---------------------------------------------------------------------------
// Per-CTA (redundant) complex Cholesky of g_S + column-parallel trisolve.
// Warp 0 only. W = R^{-1} (exact upper triangular) -> smem wbuf.
// ---------------------------------------------------------------------------
__device__ __forceinline__ void cholinv_phase(float2* __restrict__ wbuf) {
    if (threadIdx.x >= 32) return;
    const unsigned FULL = 0xffffffffu;
    const int r = threadIdx.x;

    float2 row[R_COLS];
#pragma unroll
    for (int c = 0; c < R_COLS; ++c) row[c] = __ldcg(&g_S[r * R_COLS + c]);

#pragma unroll
    for (int k = 0; k < R_COLS; ++k) {
        float dkk  = __shfl_sync(FULL, row[k].x, k);
        float invs = rsqrtf(dkk);
        float2 l;
        l.x = row[k].x * invs;
        l.y = row[k].y * invs;
        row[k] = l;
#pragma unroll
        for (int j = k + 1; j < R_COLS; ++j) {
            float lx = __shfl_sync(FULL, l.x, j);
            float ly = __shfl_sync(FULL, l.y, j);
            row[j].x -= l.x * lx + l.y * ly;
            row[j].y -= l.y * lx - l.x * ly;
        }
    }

    float2 (*L)[R_COLS] = reinterpret_cast<float2(*)[R_COLS]>(wbuf);
#pragma unroll
    for (int k = 0; k < R_COLS; ++k) L[r][k] = row[k];
    __syncwarp();

    const int c = r;
    float2 x[R_COLS];
#pragma unroll
    for (int rr = 0; rr < R_COLS; ++rr) {
        float2 s = (rr == c) ? make_float2(1.f, 0.f) : make_float2(0.f, 0.f);
#pragma unroll
        for (int k = 0; k < rr; ++k) {
            float2 lv = L[rr][k];
            s.x -= lv.x * x[k].x - lv.y * x[k].y;
            s.y -= lv.x * x[k].y + lv.y * x[k].x;
        }
        float invd = 1.0f / L[rr][rr].x;
        x[rr] = make_float2(s.x * invd, s.y * invd);
    }
    __syncwarp();   // all lanes done reading L before overwriting with W

    // W[c][j] = conj(x[j]); x[j] = 0 for j < c  -> W exactly upper triangular.
#pragma unroll
    for (int j = 0; j < R_COLS; ++j)
        wbuf[c * R_COLS + j] = make_float2(x[j].x, -x[j].y);
}

// ---------------------------------------------------------------------------
// Apply in SMEM: row' = row * W (upper tri). 2 threads per row, columns split
// by PARITY for balance (even-j sum 256 iters, odd-j 272 vs 136/392 before).
// Results written back into chunk; caller copies out coalesced.
// ---------------------------------------------------------------------------
__device__ __forceinline__ void apply_phase(float2* __restrict__ chunk,
                                            const float2* __restrict__ W) {
    const int tid = threadIdx.x;
    const int row = tid >> 1;
    const int par = tid & 1;

    float2 a[R_COLS];
    const float4* rp = reinterpret_cast<const float4*>(&chunk[row * R_COLS]);
#pragma unroll
    for (int i = 0; i < 16; ++i) {
        float4 v = rp[i];
        a[2 * i]     = make_float2(v.x, v.y);
        a[2 * i + 1] = make_float2(v.z, v.w);
    }
    __syncthreads();   // all reads done before in-place writes

    float2 res[16];
#pragma unroll
    for (int jj = 0; jj < 16; ++jj) {
        const int j = 2 * jj + par;
        float2 s = make_float2(0.f, 0.f);
#pragma unroll
        for (int i = 0; i < R_COLS; ++i) {
            if (i <= 2 * jj + 1) {          // compile-time prune near upper bound
                if (i <= j) {
                    float2 w = W[i * R_COLS + j];
                    s.x = fmaf(a[i].x, w.x, s.x);
                    s.x = fmaf(-a[i].y, w.y, s.x);
                    s.y = fmaf(a[i].x, w.y, s.y);
                    s.y = fmaf(a[i].y, w.x, s.y);
                }
            }
        }
        res[jj] = s;
    }
#pragma unroll
    for (int jj = 0; jj < 16; ++jj)
        chunk[row * R_COLS + 2 * jj + par] = res[jj];
    __syncthreads();
}

// ---------------------------------------------------------------------------
__global__ __launch_bounds__(TPB, 1) void fused_cholqr1(const float2* __restrict__ A,
                                                        float2* __restrict__ Out) {
    __shared__ float2 chunk[CHUNK * R_COLS];   // 32 KB resident rows
    __shared__ float  scratch[2048];           // 8 KB gram buf / L / W

    const int tid = threadIdx.x;
    const int blk = blockIdx.x;

    // Stage chunk (only read of A), coalesced float4.
    {
        const float4* src = reinterpret_cast<const float4*>(A + (size_t)blk * CHUNK * R_COLS);
        float4* dst = reinterpret_cast<float4*>(chunk);
#pragma unroll
        for (int i = 0; i < 8; ++i) dst[tid + TPB * i] = src[tid + TPB * i];
    }
    __syncthreads();

    float2* W = reinterpret_cast<float2*>(scratch);

    gram_phase(chunk, scratch, blk);
    grid_barrier(0);
    reduce_phase(blk);
    grid_barrier(1);
    cholinv_phase(W);
    __syncthreads();
    apply_phase(chunk, W);                      // result in chunk

    // Coalesced float4 copy-out (only write of Out).
    {
        const float4* src = reinterpret_cast<const float4*>(chunk);
        float4* dst = reinterpret_cast<float4*>(Out + (size_t)blk * CHUNK * R_COLS);
#pragma unroll
        for (int i = 0; i < 8; ++i) dst[tid + TPB * i] = src[tid + TPB * i];
    }
}

// ---------------------------------------------------------------------------
extern "C" void kernel_launch(void* const* d_in, const int* in_sizes, int n_in,
                              void* d_out, int out_size) {
    (void)in_sizes; (void)n_in; (void)out_size;
    const float2* A = reinterpret_cast<const float2*>(d_in[0]);
    float2* Out = reinterpret_cast<float2*>(d_out);

    void* barp = nullptr;
    cudaGetSymbolAddress(&barp, g_bar);
    cudaMemsetAsync(barp, 0, sizeof(unsigned) * 2);

    fused_cholqr1<<<NCTA, TPB>>>(A, Out);
}

// round 5
// speedup vs baseline: 2.1062x; 1.0128x over previous
#include <cuda_runtime.h>

// StrictOrthogonal via CholeskyQR1 (single pass), persistent kernel.
// Gaussian input (kappa ~ 1.09) -> one fp32 Cholesky-QR pass gives rel_err
// ~1e-7 (measured), threshold 1e-3. 128 CTAs x 512 threads, all co-resident
// (grid <= 148 SMs) -> software grid barrier safe. Per-CTA 128x32 complex
// chunk resident in SMEM; A read once, Out written once. 2 grid barriers.

#define M_ROWS 16384
#define R_COLS 32
#define CHUNK  128
#define NCTA   128
#define TPB    512

__device__ float    g_part[NCTA * 2048];   // per-CTA Gram partials (1 MB)
__device__ float2   g_S[R_COLS * R_COLS];  // reduced Gram
__device__ unsigned g_bar[2];              // barrier counters (memset per launch)

// ---------------------------------------------------------------------------
__device__ __forceinline__ void grid_barrier(int id) {
    __syncthreads();                       // CTA done with prior phase
    if (threadIdx.x == 0) {
        __threadfence();                   // publish this CTA's global writes
        atomicAdd(&g_bar[id], 1u);         // return unused -> no-return reduce
        volatile unsigned* p = &g_bar[id];
        while (*p < NCTA) __nanosleep(32);
        __threadfence();
    }
    __syncthreads();
}

// ---------------------------------------------------------------------------
// Gram partial over the CTA's SMEM chunk. 4 groups of 128 threads; group g
// covers rows [g*32, g*32+32). Thread tile: 2 rows x 4 cols of the 32x32
// output (ti = t&15 -> i0 = 2*ti, tj = t>>4 -> j0 = 4*tj).
// Group partials combined in-SMEM (fixed order) -> g_part[blk].
// ---------------------------------------------------------------------------
__device__ __forceinline__ void gram_phase(const float2* __restrict__ chunk,
                                           float* __restrict__ buf, int blk) {
    const int tid = threadIdx.x;
    const int g  = tid >> 7;        // 0..3
    const int t  = tid & 127;
    const int i0 = (t & 15) * 2;
    const int j0 = (t >> 4) * 4;
    const int r0 = g * 32;

    float2 acc[2][4];
#pragma unroll
    for (int p = 0; p < 2; ++p)
#pragma unroll
        for (int q = 0; q < 4; ++q) acc[p][q] = make_float2(0.f, 0.f);

#pragma unroll 8
    for (int r = 0; r < 32; ++r) {
        const float2* rowc = &chunk[(r0 + r) * R_COLS];
        float4 av = *reinterpret_cast<const float4*>(rowc + i0);
        float4 bv0 = *reinterpret_cast<const float4*>(rowc + j0);
        float4 bv1 = *reinterpret_cast<const float4*>(rowc + j0 + 2);
        float2 a[2] = { {av.x, av.y}, {av.z, av.w} };
        float2 b[4] = { {bv0.x, bv0.y}, {bv0.z, bv0.w}, {bv1.x, bv1.y}, {bv1.z, bv1.w} };
#pragma unroll
        for (int p = 0; p < 2; ++p)
#pragma unroll
            for (int q = 0; q < 4; ++q) {
                acc[p][q].x = fmaf(a[p].x, b[q].x, acc[p][q].x);
                acc[p][q].x = fmaf(a[p].y, b[q].y, acc[p][q].x);
                acc[p][q].y = fmaf(a[p].x, b[q].y, acc[p][q].y);
                acc[p][q].y = fmaf(-a[p].y, b[q].x, acc[p][q].y);
            }
    }
    __syncthreads();

#define ST_ACC() \
    { _Pragma("unroll") for (int p = 0; p < 2; ++p) _Pragma("unroll") \
      for (int q = 0; q < 4; ++q) { \
          int e = ((i0 + p) * R_COLS + (j0 + q)) * 2; \
          buf[e] = acc[p][q].x; buf[e + 1] = acc[p][q].y; } }
#define ADD_ACC() \
    { _Pragma("unroll") for (int p = 0; p < 2; ++p) _Pragma("unroll") \
      for (int q = 0; q < 4; ++q) { \
          int e = ((i0 + p) * R_COLS + (j0 + q)) * 2; \
          acc[p][q].x += buf[e]; acc[p][q].y += buf[e + 1]; } }

    if (g == 1) ST_ACC();
    __syncthreads();
    if (g == 0) ADD_ACC();
    __syncthreads();
    if (g == 3) ST_ACC();
    __syncthreads();
    if (g == 2) ADD_ACC();
    __syncthreads();
    if (g == 2) ST_ACC();
    __syncthreads();
    if (g == 0) {
        ADD_ACC();
#pragma unroll
        for (int p = 0; p < 2; ++p)
#pragma unroll
            for (int q = 0; q < 4; ++q) {
                int e = ((i0 + p) * R_COLS + (j0 + q)) * 2;
                g_part[blk * 2048 + e]     = acc[p][q].x;
                g_part[blk * 2048 + e + 1] = acc[p][q].y;
            }
    }
#undef ST_ACC
#undef ADD_ACC
}

// ---------------------------------------------------------------------------
// Reduce: 2048 elements x 128 partials. CTA owns 16 elements; 32 lanes per
// element: 4 strided __ldcg loads + 5-level shuffle tree (fixed order).
// ---------------------------------------------------------------------------
__device__ __forceinline__ void reduce_phase(int blk) {
    const int tid = threadIdx.x;
    const int e = blk * 16 + (tid >> 5);
    const int l = tid & 31;
    float s = 0.f;
#pragma unroll
    for (int k = 0; k < 4; ++k)
        s += __ldcg(&g_part[(l + 32 * k) * 2048 + e]);
    s += __shfl_down_sync(0xffffffffu, s, 16);
    s += __shfl_down_sync(0xffffffffu, s, 8);
    s += __shfl_down_sync(0xffffffffu, s, 4);
    s += __shfl_down_sync(0xffffffffu, s, 2);
    s += __shfl_down_sync(0xffffffffu, s, 1);
    if (l == 0) reinterpret_cast<float*>(g_S)[e] = s;
}

// ---------------------------------------------------------------------------
// Per-CTA (redundant) complex Cholesky of g_S + column-parallel trisolve.
// Warp 0 only. W = R^{-1} (exact upper triangular) -> smem wbuf.
// ---------------------------------------------------------------------------
__device__ __forceinline__ void cholinv_phase(float2* __restrict__ wbuf) {
    if (threadIdx.x >= 32) return;
    const unsigned FULL = 0xffffffffu;
    const int r = threadIdx.x;

    float2 row[R_COLS];
#pragma unroll
    for (int c = 0; c < R_COLS; ++c) row[c] = __ldcg(&g_S[r * R_COLS + c]);

#pragma unroll
    for (int k = 0; k < R_COLS; ++k) {
        float dkk  = __shfl_sync(FULL, row[k].x, k);
        float invs = rsqrtf(dkk);
        float2 l;
        l.x = row[k].x * invs;
        l.y = row[k].y * invs;
        row[k] = l;
#pragma unroll
        for (int j = k + 1; j < R_COLS; ++j) {
            float lx = __shfl_sync(FULL, l.x, j);
            float ly = __shfl_sync(FULL, l.y, j);
            row[j].x -= l.x * lx + l.y * ly;
            row[j].y -= l.y * lx - l.x * ly;
        }
    }

    float2 (*L)[R_COLS] = reinterpret_cast<float2(*)[R_COLS]>(wbuf);
#pragma unroll
    for (int k = 0; k < R_COLS; ++k) L[r][k] = row[k];
    __syncwarp();

    const int c = r;
    float2 x[R_COLS];
#pragma unroll
    for (int rr = 0; rr < R_COLS; ++rr) {
        float2 s = (rr == c) ? make_float2(1.f, 0.f) : make_float2(0.f, 0.f);
#pragma unroll
        for (int k = 0; k < rr; ++k) {
            float2 lv = L[rr][k];
            s.x -= lv.x * x[k].x - lv.y * x[k].y;
            s.y -= lv.x * x[k].y + lv.y * x[k].x;
        }
        float invd = 1.0f / L[rr][rr].x;
        x[rr] = make_float2(s.x * invd, s.y * invd);
    }
    __syncwarp();   // all lanes done reading L before overwriting with W

    // W[c][j] = conj(x[j]); x[j] = 0 for j < c  -> W exactly upper triangular.
#pragma unroll
    for (int j = 0; j < R_COLS; ++j)
        wbuf[c * R_COLS + j] = make_float2(x[j].x, -x[j].y);
}

// ---------------------------------------------------------------------------
// Apply in SMEM: row' = row * W (upper tri). 4 threads per row; thread c0
// handles cols j = c0, c0+4, ..., c0+28 (stride 4 -> balanced 120..144 terms).
// Results written back into chunk; caller copies out coalesced.
// ---------------------------------------------------------------------------
__device__ __forceinline__ void apply_phase(float2* __restrict__ chunk,
                                            const float2* __restrict__ W) {
    const int tid = threadIdx.x;
    const int row = tid >> 2;       // 0..127
    const int c0  = tid & 3;

    float2 a[R_COLS];
    const float4* rp = reinterpret_cast<const float4*>(&chunk[row * R_COLS]);
#pragma unroll
    for (int i = 0; i < 16; ++i) {
        float4 v = rp[i];
        a[2 * i]     = make_float2(v.x, v.y);
        a[2 * i + 1] = make_float2(v.z, v.w);
    }
    __syncthreads();   // all reads done before in-place writes

    float2 res[8];
#pragma unroll
    for (int jj = 0; jj < 8; ++jj) {
        const int j = 4 * jj + c0;
        float2 s = make_float2(0.f, 0.f);
#pragma unroll
        for (int i = 0; i < R_COLS; ++i) {
            if (i <= 4 * jj + 3) {          // compile-time prune of tail
                if (i <= j) {               // runtime triangular guard
                    float2 w = W[i * R_COLS + j];
                    s.x = fmaf(a[i].x, w.x, s.x);
                    s.x = fmaf(-a[i].y, w.y, s.x);
                    s.y = fmaf(a[i].x, w.y, s.y);
                    s.y = fmaf(a[i].y, w.x, s.y);
                }
            }
        }
        res[jj] = s;
    }
#pragma unroll
    for (int jj = 0; jj < 8; ++jj)
        chunk[row * R_COLS + 4 * jj + c0] = res[jj];
    __syncthreads();
}

// ---------------------------------------------------------------------------
__global__ __launch_bounds__(TPB, 1) void fused_cholqr1(const float2* __restrict__ A,
                                                        float2* __restrict__ Out) {
    __shared__ float2 chunk[CHUNK * R_COLS];   // 32 KB resident rows
    __shared__ float  scratch[2048];           // 8 KB gram buf / L / W

    const int tid = threadIdx.x;
    const int blk = blockIdx.x;

    // Stage chunk (only read of A), coalesced float4: 2048 float4 / 512 thr.
    {
        const float4* src = reinterpret_cast<const float4*>(A + (size_t)blk * CHUNK * R_COLS);
        float4* dst = reinterpret_cast<float4*>(chunk);
#pragma unroll
        for (int i = 0; i < 4; ++i) dst[tid + TPB * i] = src[tid + TPB * i];
    }
    __syncthreads();

    float2* W = reinterpret_cast<float2*>(scratch);

    gram_phase(chunk, scratch, blk);
    grid_barrier(0);
    reduce_phase(blk);
    grid_barrier(1);
    cholinv_phase(W);
    __syncthreads();
    apply_phase(chunk, W);                      // result in chunk

    // Coalesced float4 copy-out (only write of Out).
    {
        const float4* src = reinterpret_cast<const float4*>(chunk);
        float4* dst = reinterpret_cast<float4*>(Out + (size_t)blk * CHUNK * R_COLS);
#pragma unroll
        for (int i = 0; i < 4; ++i) dst[tid + TPB * i] = src[tid + TPB * i];
    }
}

// ---------------------------------------------------------------------------
extern "C" void kernel_launch(void* const* d_in, const int* in_sizes, int n_in,
                              void* d_out, int out_size) {
    (void)in_sizes; (void)n_in; (void)out_size;
    const float2* A = reinterpret_cast<const float2*>(d_in[0]);
    float2* Out = reinterpret_cast<float2*>(d_out);

    void* barp = nullptr;
    cudaGetSymbolAddress(&barp, g_bar);
    cudaMemsetAsync(barp, 0, sizeof(unsigned) * 2);

    fused_cholqr1<<<NCTA, TPB>>>(A, Out);
}